// round 17
// baseline (speedup 1.0000x reference)
#include <cuda_runtime.h>
#include <math.h>

#define NP 256        // particles
#define ND 3
#define NR 64         // rbfs
#define NH 128        // hidden
#define NB 16         // batch
#define FEPS 1e-6f

#define K_TAB 256
#define D_MAX 12.0f

#define N_BUILD  32                 // builder blocks = lowest 32 block ids
#define E_PER_BB (K_TAB / N_BUILD)  // 8 table entries per builder block
#define EL_TOT   (E_PER_BB + 2)     // + 1-entry halo each side

__device__ float4 coef_tab[K_TAB];  // u-form quadratic coeffs of -2*g(d)
__device__ int    tab_flag;         // builders-done counter (memset 0 per launch)

__device__ __forceinline__ unsigned long long pack2(float lo, float hi) {
    unsigned long long p;
    asm("mov.b64 %0, {%1, %2};" : "=l"(p) : "f"(lo), "f"(hi));
    return p;
}

__device__ __forceinline__ float fast_tanh(float a) {
    float e = __expf(2.0f * a);
    return 1.0f - __fdividef(2.0f, e + 1.0f);
}

// Shared memory union: force path 8 KB, builder path ~5.3 KB.
union Smem {
    struct {
        float4 pos[NP];        // 4 KB
        float4 coef[K_TAB];    // 4 KB
    } f;
    struct {
        unsigned long long rbf[EL_TOT][NR];  // 5 KB
        float partial[EL_TOT][4];
        float T[EL_TOT];
    } b;
};

// ---------------------------------------------------------------------------
// Fused kernel, 1D grid of N_BUILD + 16*NB = 288 blocks x 256 threads.
// __launch_bounds__(256,2) caps regs at 128 -> ALL 288 blocks co-resident on
// 148 SMs (cap 296); builders hold the lowest block ids (scheduled first).
// Either property alone rules out spin deadlock.
//  - Builders (bid < 32): tabulate -2*g(d) + u-form quadratic coeffs for 8
//    entries (+halo). Publish: per-thread __threadfence() BEFORE the barrier
//    (R14 bug: only tid0 fenced, leaving threads 1-7's coef stores unordered
//    w.r.t. the flag), then tid0 atomicAdd(tab_flag).
//  - Force blocks: stage positions, run table-independent phases A-D
//    (diff/d2/rsqrt/u, held live -> overlaps builder execution), spin on
//    tab_flag, stage coef to smem via L2 (__ldcg), then phase E + reduce.
// CoM mean subtraction skipped (pair antisymmetry: mean is rounding noise).
// ---------------------------------------------------------------------------
__global__ __launch_bounds__(256, 2) void fused_kernel(
    const float* __restrict__ xs,
    const float* __restrict__ mus, const float* __restrict__ log_gammas,
    const float* __restrict__ W1, const float* __restrict__ b1,
    const float* __restrict__ W2,
    float* __restrict__ out)
{
    __shared__ Smem smem;
    const int tid = threadIdx.x;

    if (blockIdx.x < N_BUILD) {
        // ================= builder path =================
        const int bb     = blockIdx.x;            // 0..31
        const int e_base = bb * E_PER_BB;
        const int h      = tid & 127;             // hidden unit
        const int sub    = tid >> 7;              // 0/1: entry parity this pass
        const float step = D_MAX / (float)(K_TAB - 1);

        // Phase 1: rbf/drbf for EL_TOT*NR = 640 (entry, r) slots
#pragma unroll
        for (int it = 0; it < 3; it++) {
            int idx = it * 256 + tid;
            if (idx < EL_TOT * NR) {
                int el = idx >> 6, r = idx & 63;
                int e  = min(max(e_base - 1 + el, 0), K_TAB - 1);
                float d   = (float)e * step;
                float gma = __expf(log_gammas[r]);
                float dm  = d - mus[r];
                float ex  = __expf(-gma * dm * dm);
                smem.b.rbf[el][r] = pack2(ex, -2.0f * gma * dm * ex);
            }
        }

        float w[NR];
#pragma unroll
        for (int r = 0; r < NR; r++) w[r] = W1[r * NH + h];
        const float b1h = b1[h];
        const float W2h = W2[h];
        __syncthreads();

        const int wsub = (tid >> 5) & 3;
#pragma unroll
        for (int p = 0; p < EL_TOT / 2; p++) {
            const int el = p * 2 + sub;
            unsigned long long acc0 = pack2(b1h, 0.0f);   // {a, sb}
            unsigned long long acc1 = pack2(0.0f, 0.0f);
            unsigned long long acc2 = pack2(0.0f, 0.0f);
            unsigned long long acc3 = pack2(0.0f, 0.0f);
            const unsigned long long* rb = smem.b.rbf[el];
#pragma unroll
            for (int r = 0; r < NR; r += 4) {
                unsigned long long w0, w1, w2, w3;
                asm("mov.b64 %0, {%1, %1};" : "=l"(w0) : "f"(w[r + 0]));
                asm("mov.b64 %0, {%1, %1};" : "=l"(w1) : "f"(w[r + 1]));
                asm("mov.b64 %0, {%1, %1};" : "=l"(w2) : "f"(w[r + 2]));
                asm("mov.b64 %0, {%1, %1};" : "=l"(w3) : "f"(w[r + 3]));
                asm("fma.rn.f32x2 %0, %1, %2, %0;" : "+l"(acc0) : "l"(rb[r + 0]), "l"(w0));
                asm("fma.rn.f32x2 %0, %1, %2, %0;" : "+l"(acc1) : "l"(rb[r + 1]), "l"(w1));
                asm("fma.rn.f32x2 %0, %1, %2, %0;" : "+l"(acc2) : "l"(rb[r + 2]), "l"(w2));
                asm("fma.rn.f32x2 %0, %1, %2, %0;" : "+l"(acc3) : "l"(rb[r + 3]), "l"(w3));
            }
            float a0, s0, a1, s1, a2, s2, a3, s3;
            asm("mov.b64 {%0, %1}, %2;" : "=f"(a0), "=f"(s0) : "l"(acc0));
            asm("mov.b64 {%0, %1}, %2;" : "=f"(a1), "=f"(s1) : "l"(acc1));
            asm("mov.b64 {%0, %1}, %2;" : "=f"(a2), "=f"(s2) : "l"(acc2));
            asm("mov.b64 {%0, %1}, %2;" : "=f"(a3), "=f"(s3) : "l"(acc3));
            float a  = (a0 + a1) + (a2 + a3);
            float sb = (s0 + s1) + (s2 + s3);
            float t  = fast_tanh(a);
            float contrib = W2h * (1.0f - t * t) * sb;
#pragma unroll
            for (int off = 16; off > 0; off >>= 1)
                contrib += __shfl_xor_sync(0xFFFFFFFFu, contrib, off);
            if ((tid & 31) == 0) smem.b.partial[el][wsub] = contrib;
        }
        __syncthreads();

        if (tid < EL_TOT)
            smem.b.T[tid] = -2.0f * (smem.b.partial[tid][0] + smem.b.partial[tid][1]
                                   + smem.b.partial[tid][2] + smem.b.partial[tid][3]);
        __syncthreads();

        if (tid < E_PER_BB) {
            const int k = e_base + tid;
            float gm = smem.b.T[tid], g0 = smem.b.T[tid + 1], gp = smem.b.T[tid + 2];
            float c1 = 0.5f * (gp - gm);
            float c2 = 0.5f * (gp - 2.0f * g0 + gm);
            float fk = (float)k;
            float c1u = c1 - 2.0f * c2 * fk;
            float c0u = g0 - fk * (c1 - c2 * fk);
            coef_tab[k] = make_float4(c0u, c1u, c2, 0.0f);
        }
        // publish: EVERY thread fences its stores, then barrier, then release
        __threadfence();
        __syncthreads();
        if (tid == 0) atomicAdd(&tab_flag, 1);
        return;
    }

    // ================= force path =================
    const int fid  = blockIdx.x - N_BUILD;    // 0..255
    const int b    = fid >> 4;                // batch
    const int xblk = fid & 15;                // i-tile
    const float* xb = xs + (size_t)b * NP * ND;

    smem.f.pos[tid] = make_float4(__ldg(xb + tid * 3 + 0),
                                  __ldg(xb + tid * 3 + 1),
                                  __ldg(xb + tid * 3 + 2), 0.0f);
    __syncthreads();

    const int i = xblk * 16 + (tid >> 4);
    const int q = tid & 15;
    const float4 pi = smem.f.pos[i];
    const float xi = pi.x, yi = pi.y, zi = pi.z;
    const float inv_step = (float)(K_TAB - 1) / D_MAX;

    float rx[16], ry[16], rz[16], invd[16], uu[16];

    // Phases A-D: table-independent (runs concurrently with builders)
#pragma unroll
    for (int m = 0; m < 16; m++) {
        float4 pj = smem.f.pos[m * 16 + q];
        rx[m] = xi - pj.x;
        ry[m] = yi - pj.y;
        rz[m] = zi - pj.z;
        float d2 = fmaf(rx[m], rx[m], fmaf(ry[m], ry[m], fmaf(rz[m], rz[m], FEPS)));
        invd[m] = rsqrtf(d2);
        uu[m]   = fminf(d2 * invd[m] * inv_step, (float)(K_TAB - 2));
    }

    // wait for all builders
    if (tid == 0) {
        while (atomicAdd(&tab_flag, 0) < N_BUILD) { }
    }
    __syncthreads();
    __threadfence();

    // stage coef table (L2-coherent; builders fenced their stores)
    smem.f.coef[tid] = __ldcg(&coef_tab[tid]);
    __syncthreads();

    // Phase E: interpolate + accumulate
    float ax = 0.f, ay = 0.f, az = 0.f;
#pragma unroll
    for (int m = 0; m < 16; m++) {
        int k = __float2int_rd(uu[m]);
        float4 c = smem.f.coef[k];
        float g  = fmaf(uu[m], fmaf(uu[m], c.z, c.y), c.x);
        float s  = g * invd[m];          // j==i: r=0 -> contributes 0
        ax = fmaf(s, rx[m], ax);
        ay = fmaf(s, ry[m], ay);
        az = fmaf(s, rz[m], az);
    }

#pragma unroll
    for (int off = 1; off < 16; off <<= 1) {
        ax += __shfl_xor_sync(0xFFFFFFFFu, ax, off);
        ay += __shfl_xor_sync(0xFFFFFFFFu, ay, off);
        az += __shfl_xor_sync(0xFFFFFFFFu, az, off);
    }

    if (q == 0) {
        float* o = out + ((size_t)b * NP + i) * 3;
        o[0] = ax;    // -2 factor baked into coef_tab
        o[1] = ay;
        o[2] = az;
    }
}

// ---------------------------------------------------------------------------
// Inputs (metadata order): t(1), xs(12288), mus(64), log_gammas(64),
//                          W1(8192), b1(128), W2(128), b2(1)
// Output: float32 (16, 256, 3)
// ---------------------------------------------------------------------------
extern "C" void kernel_launch(void* const* d_in, const int* in_sizes, int n_in,
                              void* d_out, int out_size)
{
    const float* xs  = (const float*)d_in[1];
    const float* mus = (const float*)d_in[2];
    const float* lg  = (const float*)d_in[3];
    const float* W1  = (const float*)d_in[4];
    const float* b1  = (const float*)d_in[5];
    const float* W2  = (const float*)d_in[6];
    float* out = (float*)d_out;

    void* flag_ptr = nullptr;
    cudaGetSymbolAddress(&flag_ptr, tab_flag);
    cudaMemsetAsync(flag_ptr, 0, sizeof(int));

    fused_kernel<<<N_BUILD + 16 * NB, 256>>>(xs, mus, lg, W1, b1, W2, out);
}